// round 3
// baseline (speedup 1.0000x reference)
#include <cuda_runtime.h>
#include <cstddef>

// SpanRepresentation: out[b, s, :] = concat(x[b, start(s), :], x[b, end(s), :], wemb[wid(s), :])
// Shapes fixed by the dataset: B=16, L=512, D=768, W=8, WD=64.
// Spans ordered by width w=1..8, within width by start=0..L-w.

constexpr int B   = 16;
constexpr int L   = 512;
constexpr int D   = 768;
constexpr int W   = 8;
constexpr int WD  = 64;

// n_w = L - w + 1 ; cumulative offsets for w = 1..8
// 0, 512, 1023, 1533, 2042, 2550, 3057, 3563, (4068)
constexpr int NS  = 4068;

constexpr int ROWF = 2 * D + WD;   // 1600 floats per output row
constexpr int ROW4 = ROWF / 4;     // 400 float4
constexpr int D4   = D / 4;        // 192
constexpr int WD4  = WD / 4;       // 16

__global__ __launch_bounds__(128, 16)
void span_repr_kernel(const float4* __restrict__ x,      // [B, L, D/4]
                      const float4* __restrict__ wemb,   // [W, WD/4]
                      float4* __restrict__ out)          // [B*NS, ROW4]
{
    const int row = blockIdx.x;          // 0 .. B*NS-1
    const int b   = row / NS;
    const int s   = row - b * NS;

    // Resolve width bucket from span index (block-uniform; 7 compares).
    int wid = 0;
    wid += (s >= 512);
    wid += (s >= 1023);
    wid += (s >= 1533);
    wid += (s >= 2042);
    wid += (s >= 2550);
    wid += (s >= 3057);
    wid += (s >= 3563);

    // start offset within this width bucket
    // off[wid] selected via arithmetic (tiny select chain, uniform)
    int off;
    switch (wid) {
        case 0: off = 0;    break;
        case 1: off = 512;  break;
        case 2: off = 1023; break;
        case 3: off = 1533; break;
        case 4: off = 2042; break;
        case 5: off = 2550; break;
        case 6: off = 3057; break;
        default: off = 3563; break;
    }
    const int start = s - off;
    const int end   = start + wid;       // width = wid+1 -> end = start + width - 1

    const float4* __restrict__ xs = x    + ((size_t)b * L + start) * D4;
    const float4* __restrict__ xe = x    + ((size_t)b * L + end)   * D4;
    const float4* __restrict__ wf = wemb + (size_t)wid * WD4;
    float4* __restrict__ o        = out  + (size_t)row * ROW4;

    // 400 float4 per row; boundaries 192 and 384 are warp-aligned under stride 128.
    #pragma unroll
    for (int j = threadIdx.x; j < ROW4; j += 128) {
        float4 v;
        if (j < D4) {
            v = __ldg(&xs[j]);
        } else if (j < 2 * D4) {
            v = __ldg(&xe[j - D4]);
        } else {
            v = __ldg(&wf[j - 2 * D4]);
        }
        // Streaming store: output is touched exactly once; keep x resident in L2.
        __stcs(&o[j], v);
    }
}

extern "C" void kernel_launch(void* const* d_in, const int* in_sizes, int n_in,
                              void* d_out, int out_size)
{
    const float4* x    = (const float4*)d_in[0];   // x: [16, 512, 768] fp32
    const float4* wemb = (const float4*)d_in[1];   // width_emb: [8, 64] fp32
    float4* out        = (float4*)d_out;           // [16, 4068, 1600] fp32

    (void)in_sizes; (void)n_in; (void)out_size;

    dim3 grid(B * NS);   // 65088 CTAs
    dim3 block(128);
    span_repr_kernel<<<grid, block>>>(x, wemb, out);
}